// round 4
// baseline (speedup 1.0000x reference)
#include <cuda_runtime.h>
#include <math.h>

#define Bsz 32
#define Rr  64
#define Ll  4096
#define Hh  768

// Scratch (no device mallocs allowed)
__device__ float g_v[Bsz * Hh];   // v[b,h] = sum_k W[h,k] * ans[b,k]
__device__ float g_t[Bsz * Ll];   // t[b,l] = hidden[b,l,:] . v[b,:]

// ---------------------------------------------------------------------------
// Kernel 1: batched GEMV  v[b,h] = W[h,:] . ans[b,:]
// block = (32 b-lanes, 8 h-rows), grid = H/8 = 96.
// W row load is warp-uniform (broadcast); ans rows stay L1-resident (96 KB).
// ---------------------------------------------------------------------------
__global__ void k_gemv(const float* __restrict__ W, const float* __restrict__ ans) {
    const int b  = threadIdx.x;               // 0..31
    const int h  = blockIdx.x * 8 + threadIdx.y;
    const float4* wrow = (const float4*)(W   + (size_t)h * Hh);
    const float4* arow = (const float4*)(ans + (size_t)b * Hh);
    float acc = 0.f;
#pragma unroll 4
    for (int k = 0; k < Hh / 4; k++) {
        float4 w4 = wrow[k];
        float4 a4 = arow[k];
        acc += w4.x * a4.x + w4.y * a4.y + w4.z * a4.z + w4.w * a4.w;
    }
    g_v[b * Hh + h] = acc;
}

// ---------------------------------------------------------------------------
// Kernel 2: t[b,l] = hidden[b,l,:] . v[b,:]    — the 402 MB HBM stream.
// One warp per token, 8 tokens/warp, 8 warps/block, 64 tokens/block.
// Lane-strided float4 loads: 6 independent LDG.128 per lane per token (MLP).
// grid = (L/64, B) = (64, 32) = 2048 blocks.
// ---------------------------------------------------------------------------
__global__ void k_dot(const float* __restrict__ hidden) {
    __shared__ float4 sv[Hh / 4];
    const int b = blockIdx.y;

    for (int i = threadIdx.x; i < Hh / 4; i += blockDim.x)
        sv[i] = ((const float4*)(g_v + b * Hh))[i];
    __syncthreads();

    const int warp = threadIdx.x >> 5;
    const int lane = threadIdx.x & 31;
    const int l0   = blockIdx.x * 64 + warp * 8;   // this warp's 8 tokens

    const float4* base = (const float4*)(hidden + ((size_t)b * Ll + l0) * Hh);

#pragma unroll
    for (int i = 0; i < 8; i++) {
        float acc = 0.f;
#pragma unroll
        for (int k = 0; k < 6; k++) {
            float4 x  = base[(size_t)i * (Hh / 4) + lane + k * 32];
            float4 vv = sv[lane + k * 32];
            acc += x.x * vv.x + x.y * vv.y + x.z * vv.z + x.w * vv.w;
        }
#pragma unroll
        for (int o = 16; o; o >>= 1)
            acc += __shfl_down_sync(0xffffffffu, acc, o);
        if (lane == 0)
            g_t[b * Ll + l0 + i] = acc;
    }
}

// ---------------------------------------------------------------------------
// Kernel 3: span-mean over t, mask, bias, softmax per batch row.
// One block per b; 8 warps, warp per span (8 spans each); t is L2-hot.
// NOTE: rubric_mask is a bool input -> harness promotes it to int32.
// ---------------------------------------------------------------------------
__global__ void k_score(const int* __restrict__ span,
                        const int* __restrict__ mask,
                        const float* __restrict__ bias,
                        float* __restrict__ out) {
    __shared__ float sc[Rr];
    const int b    = blockIdx.x;
    const int warp = threadIdx.x >> 5;
    const int lane = threadIdx.x & 31;

    for (int r = warp; r < Rr; r += 8) {
        float score;
        if (mask[b * Rr + r] == 0) {
            score = -INFINITY;
        } else {
            const int s = span[(b * Rr + r) * 2 + 0];
            const int e = span[(b * Rr + r) * 2 + 1];
            const float* t = g_t + b * Ll;
            float acc = 0.f;
            for (int idx = s + lane; idx < e; idx += 32)
                acc += t[idx];
#pragma unroll
            for (int o = 16; o; o >>= 1)
                acc += __shfl_down_sync(0xffffffffu, acc, o);
            int len = e - s; if (len < 1) len = 1;
            score = acc / (float)len + bias[0];
        }
        if (lane == 0) sc[r] = score;
    }
    __syncthreads();

    if (threadIdx.x < 32) {
        const int tid = threadIdx.x;
        float a0 = sc[tid], a1 = sc[tid + 32];
        float m = fmaxf(a0, a1);
#pragma unroll
        for (int o = 16; o; o >>= 1)
            m = fmaxf(m, __shfl_xor_sync(0xffffffffu, m, o));
        float e0 = expf(a0 - m);
        float e1 = expf(a1 - m);
        float ssum = e0 + e1;
#pragma unroll
        for (int o = 16; o; o >>= 1)
            ssum += __shfl_xor_sync(0xffffffffu, ssum, o);
        out[b * Rr + tid]      = e0 / ssum;
        out[b * Rr + tid + 32] = e1 / ssum;
    }
}

// ---------------------------------------------------------------------------
extern "C" void kernel_launch(void* const* d_in, const int* in_sizes, int n_in,
                              void* d_out, int out_size) {
    const float* ans    = (const float*)d_in[0];   // (32, 768) f32
    const float* hidden = (const float*)d_in[1];   // (32, 4096, 768) f32
    const int*   span   = (const int*)d_in[2];     // (32, 64, 2) i32
    const int*   mask   = (const int*)d_in[3];     // (32, 64) bool -> i32
    const float* W      = (const float*)d_in[4];   // (1, 768, 768) f32
    const float* bias   = (const float*)d_in[5];   // (1,) f32
    float*       out    = (float*)d_out;           // (32, 64) f32

    k_gemv <<< Hh / 8, dim3(32, 8) >>> (W, ans);
    k_dot  <<< dim3(Ll / 64, Bsz), 256 >>> (hidden);
    k_score<<< Bsz, 256 >>> (span, mask, bias, out);
}

// round 5
// speedup vs baseline: 1.3980x; 1.3980x over previous
#include <cuda_runtime.h>
#include <math.h>

#define Bsz 32
#define Rr  64
#define Ll  4096
#define Hh  768

// Scratch (no device mallocs allowed)
__device__ float g_v[Bsz * Hh];   // v[b,h] = sum_k W[h,k] * ans[b,k]
__device__ float g_t[Bsz * Ll];   // t[b,l] = hidden[b,l,:] . v[b,:]

// ---------------------------------------------------------------------------
// Kernel 1: batched GEMV  v[b,h] = W[h,:] . ans[b,:]
// One warp per h-row, serving 4 batches; W fragment held in registers and
// reused across the 4 batches (W L2 traffic = 8x W = 19 MB).
// grid = (H/8 = 96, B/4 = 8) = 768 blocks, 8 warps/block -> fills the chip.
// ---------------------------------------------------------------------------
__global__ void k_gemv(const float* __restrict__ W, const float* __restrict__ ans) {
    const int warp = threadIdx.x >> 5;
    const int lane = threadIdx.x & 31;
    const int h    = blockIdx.x * 8 + warp;
    const int b0   = blockIdx.y * 4;

    // Load this warp's W-row fragment: 6 x float4 per lane, lane-strided.
    const float4* wrow = (const float4*)(W + (size_t)h * Hh);
    float4 w[6];
#pragma unroll
    for (int k = 0; k < 6; k++) w[k] = wrow[lane + k * 32];

#pragma unroll
    for (int j = 0; j < 4; j++) {
        const int b = b0 + j;
        const float4* arow = (const float4*)(ans + (size_t)b * Hh);
        float acc = 0.f;
#pragma unroll
        for (int k = 0; k < 6; k++) {
            float4 a4 = arow[lane + k * 32];
            acc += w[k].x * a4.x + w[k].y * a4.y + w[k].z * a4.z + w[k].w * a4.w;
        }
#pragma unroll
        for (int o = 16; o; o >>= 1)
            acc += __shfl_down_sync(0xffffffffu, acc, o);
        if (lane == 0)
            g_v[b * Hh + h] = acc;
    }
}

// ---------------------------------------------------------------------------
// Kernel 2: t[b,l] = hidden[b,l,:] . v[b,:]    — the 402 MB HBM stream.
// One warp per token, 8 tokens/warp, 8 warps/block, 64 tokens/block.
// Lane-strided float4 __ldcs loads (streaming, evict-first).
// grid = (L/64, B) = (64, 32) = 2048 blocks.
// ---------------------------------------------------------------------------
__global__ void k_dot(const float* __restrict__ hidden) {
    __shared__ float4 sv[Hh / 4];
    const int b = blockIdx.y;

    for (int i = threadIdx.x; i < Hh / 4; i += blockDim.x)
        sv[i] = ((const float4*)(g_v + b * Hh))[i];
    __syncthreads();

    const int warp = threadIdx.x >> 5;
    const int lane = threadIdx.x & 31;
    const int l0   = blockIdx.x * 64 + warp * 8;   // this warp's 8 tokens

    const float4* base = (const float4*)(hidden + ((size_t)b * Ll + l0) * Hh);

#pragma unroll
    for (int i = 0; i < 8; i++) {
        float acc = 0.f;
#pragma unroll
        for (int k = 0; k < 6; k++) {
            float4 x  = __ldcs(&base[(size_t)i * (Hh / 4) + lane + k * 32]);
            float4 vv = sv[lane + k * 32];
            acc += x.x * vv.x + x.y * vv.y + x.z * vv.z + x.w * vv.w;
        }
#pragma unroll
        for (int o = 16; o; o >>= 1)
            acc += __shfl_down_sync(0xffffffffu, acc, o);
        if (lane == 0)
            g_t[b * Ll + l0 + i] = acc;
    }
}

// ---------------------------------------------------------------------------
// Kernel 3: span-mean over t, mask, bias, softmax per batch row.
// One block per b; 8 warps, warp per span (8 spans each); t is L2-hot.
// NOTE: rubric_mask is bool -> harness promotes to int32.
// ---------------------------------------------------------------------------
__global__ void k_score(const int* __restrict__ span,
                        const int* __restrict__ mask,
                        const float* __restrict__ bias,
                        float* __restrict__ out) {
    __shared__ float sc[Rr];
    const int b    = blockIdx.x;
    const int warp = threadIdx.x >> 5;
    const int lane = threadIdx.x & 31;

    for (int r = warp; r < Rr; r += 8) {
        float score;
        if (mask[b * Rr + r] == 0) {
            score = -INFINITY;
        } else {
            const int s = span[(b * Rr + r) * 2 + 0];
            const int e = span[(b * Rr + r) * 2 + 1];
            const float* t = g_t + b * Ll;
            float acc = 0.f;
            for (int idx = s + lane; idx < e; idx += 32)
                acc += t[idx];
#pragma unroll
            for (int o = 16; o; o >>= 1)
                acc += __shfl_down_sync(0xffffffffu, acc, o);
            int len = e - s; if (len < 1) len = 1;
            score = acc / (float)len + bias[0];
        }
        if (lane == 0) sc[r] = score;
    }
    __syncthreads();

    if (threadIdx.x < 32) {
        const int tid = threadIdx.x;
        float a0 = sc[tid], a1 = sc[tid + 32];
        float m = fmaxf(a0, a1);
#pragma unroll
        for (int o = 16; o; o >>= 1)
            m = fmaxf(m, __shfl_xor_sync(0xffffffffu, m, o));
        float e0 = expf(a0 - m);
        float e1 = expf(a1 - m);
        float ssum = e0 + e1;
#pragma unroll
        for (int o = 16; o; o >>= 1)
            ssum += __shfl_xor_sync(0xffffffffu, ssum, o);
        out[b * Rr + tid]      = e0 / ssum;
        out[b * Rr + tid + 32] = e1 / ssum;
    }
}

// ---------------------------------------------------------------------------
extern "C" void kernel_launch(void* const* d_in, const int* in_sizes, int n_in,
                              void* d_out, int out_size) {
    const float* ans    = (const float*)d_in[0];   // (32, 768) f32
    const float* hidden = (const float*)d_in[1];   // (32, 4096, 768) f32
    const int*   span   = (const int*)d_in[2];     // (32, 64, 2) i32
    const int*   mask   = (const int*)d_in[3];     // (32, 64) bool -> i32
    const float* W      = (const float*)d_in[4];   // (1, 768, 768) f32
    const float* bias   = (const float*)d_in[5];   // (1,) f32
    float*       out    = (float*)d_out;           // (32, 64) f32

    k_gemv <<< dim3(Hh / 8, Bsz / 4), 256 >>> (W, ans);
    k_dot  <<< dim3(Ll / 64, Bsz), 256 >>> (hidden);
    k_score<<< Bsz, 256 >>> (span, mask, bias, out);
}

// round 7
// speedup vs baseline: 1.4637x; 1.0470x over previous
#include <cuda_runtime.h>
#include <math.h>

#define Bsz 32
#define Rr  64
#define Ll  4096
#define Hh  768

// Scratch (no device mallocs allowed)
__device__ float g_v[Bsz * Hh];   // v[b,h] = sum_k W[h,k] * ans[b,k]
__device__ float g_t[Bsz * Ll];   // t[b,l] = hidden[b,l,:] . v[b,:]

// ---------------------------------------------------------------------------
// Kernel 1: batched GEMV  v[b,h] = W[h,:] . ans[b,:]
// One warp per h-row, serving 4 batches; W fragment held in registers and
// reused across the 4 batches. block=128 (4 warps), grid=(H/4, B/4)=1536
// blocks for better chip fill / shorter tail than the 768-block version.
// ---------------------------------------------------------------------------
__global__ void k_gemv(const float* __restrict__ W, const float* __restrict__ ans) {
    const int warp = threadIdx.x >> 5;
    const int lane = threadIdx.x & 31;
    const int h    = blockIdx.x * 4 + warp;
    const int b0   = blockIdx.y * 4;

    const float4* wrow = (const float4*)(W + (size_t)h * Hh);
    float4 w[6];
#pragma unroll
    for (int k = 0; k < 6; k++) w[k] = wrow[lane + k * 32];

#pragma unroll
    for (int j = 0; j < 4; j++) {
        const int b = b0 + j;
        const float4* arow = (const float4*)(ans + (size_t)b * Hh);
        float acc = 0.f;
#pragma unroll
        for (int k = 0; k < 6; k++) {
            float4 a4 = arow[lane + k * 32];
            acc += w[k].x * a4.x + w[k].y * a4.y + w[k].z * a4.z + w[k].w * a4.w;
        }
#pragma unroll
        for (int o = 16; o; o >>= 1)
            acc += __shfl_down_sync(0xffffffffu, acc, o);
        if (lane == 0)
            g_v[b * Hh + h] = acc;
    }
}

// ---------------------------------------------------------------------------
// Kernel 2: t[b,l] = hidden[b,l,:] . v[b,:]    — the 402 MB HBM stream.
// One warp per token, 16 tokens/warp, 8 warps/block, 128 tokens/block.
// grid = (L/128, B) = (32, 32) = 1024 blocks; __launch_bounds__(256,8)
// forces regs <= 32 so 8 blocks/SM fit -> 1184 capacity -> SINGLE WAVE.
// ---------------------------------------------------------------------------
__global__ void __launch_bounds__(256, 8)
k_dot(const float* __restrict__ hidden) {
    __shared__ float4 sv[Hh / 4];
    const int b = blockIdx.y;

    for (int i = threadIdx.x; i < Hh / 4; i += blockDim.x)
        sv[i] = ((const float4*)(g_v + b * Hh))[i];
    __syncthreads();

    const int warp = threadIdx.x >> 5;
    const int lane = threadIdx.x & 31;
    const int l0   = blockIdx.x * 128 + warp * 16;   // this warp's 16 tokens

    const float4* base = (const float4*)(hidden + ((size_t)b * Ll + l0) * Hh) + lane;

    for (int i = 0; i < 16; i++) {
        float acc = 0.f;
#pragma unroll
        for (int k = 0; k < 6; k++) {
            float4 x  = __ldcs(base + (size_t)i * (Hh / 4) + k * 32);
            float4 vv = sv[lane + k * 32];
            acc += x.x * vv.x + x.y * vv.y + x.z * vv.z + x.w * vv.w;
        }
#pragma unroll
        for (int o = 16; o; o >>= 1)
            acc += __shfl_down_sync(0xffffffffu, acc, o);
        if (lane == 0)
            g_t[b * Ll + l0 + i] = acc;
    }
}

// ---------------------------------------------------------------------------
// Kernel 3: span-mean over t, mask, bias, softmax per batch row.
// One block per b; 8 warps, warp per span (8 spans each); t is L2-hot.
// NOTE: rubric_mask is bool -> harness promotes to int32.
// ---------------------------------------------------------------------------
__global__ void k_score(const int* __restrict__ span,
                        const int* __restrict__ mask,
                        const float* __restrict__ bias,
                        float* __restrict__ out) {
    __shared__ float sc[Rr];
    const int b    = blockIdx.x;
    const int warp = threadIdx.x >> 5;
    const int lane = threadIdx.x & 31;

    for (int r = warp; r < Rr; r += 8) {
        float score;
        if (mask[b * Rr + r] == 0) {
            score = -INFINITY;
        } else {
            const int s = span[(b * Rr + r) * 2 + 0];
            const int e = span[(b * Rr + r) * 2 + 1];
            const float* t = g_t + b * Ll;
            float acc = 0.f;
            for (int idx = s + lane; idx < e; idx += 32)
                acc += t[idx];
#pragma unroll
            for (int o = 16; o; o >>= 1)
                acc += __shfl_down_sync(0xffffffffu, acc, o);
            int len = e - s; if (len < 1) len = 1;
            score = acc / (float)len + bias[0];
        }
        if (lane == 0) sc[r] = score;
    }
    __syncthreads();

    if (threadIdx.x < 32) {
        const int tid = threadIdx.x;
        float a0 = sc[tid], a1 = sc[tid + 32];
        float m = fmaxf(a0, a1);
#pragma unroll
        for (int o = 16; o; o >>= 1)
            m = fmaxf(m, __shfl_xor_sync(0xffffffffu, m, o));
        float e0 = expf(a0 - m);
        float e1 = expf(a1 - m);
        float ssum = e0 + e1;
#pragma unroll
        for (int o = 16; o; o >>= 1)
            ssum += __shfl_xor_sync(0xffffffffu, ssum, o);
        out[b * Rr + tid]      = e0 / ssum;
        out[b * Rr + tid + 32] = e1 / ssum;
    }
}

// ---------------------------------------------------------------------------
extern "C" void kernel_launch(void* const* d_in, const int* in_sizes, int n_in,
                              void* d_out, int out_size) {
    const float* ans    = (const float*)d_in[0];   // (32, 768) f32
    const float* hidden = (const float*)d_in[1];   // (32, 4096, 768) f32
    const int*   span   = (const int*)d_in[2];     // (32, 64, 2) i32
    const int*   mask   = (const int*)d_in[3];     // (32, 64) bool -> i32
    const float* W      = (const float*)d_in[4];   // (1, 768, 768) f32
    const float* bias   = (const float*)d_in[5];   // (1,) f32
    float*       out    = (float*)d_out;           // (32, 64) f32

    k_gemv <<< dim3(Hh / 4, Bsz / 4), 128 >>> (W, ans);
    k_dot  <<< dim3(Ll / 128, Bsz), 256 >>> (hidden);
    k_score<<< Bsz, 256 >>> (span, mask, bias, out);
}